// round 13
// baseline (speedup 1.0000x reference)
#include <cuda_runtime.h>

// InteractiveGallingModelV6 — v4: warp-specialized producer/consumer.
// R12 falsified the load-latency model (depth-4 == depth-2). New theory:
// chain warps stall on STG backpressure (bursty stores, 2 warps/SMSP).
// Fix: 4 producer warps compute the recurrence and stage results in SMEM;
// 4 consumer warps drain SMEM -> GMEM with STG.128. Double buffer, named
// barriers (bar.arrive/bar.sync producer-consumer idiom).

#define N_CYCLES 150
#define BATCH    65536
#define HALF     (BATCH / 2)            // float2 lanes total
#define LANES_PER_CTA 256               // floats per CTA per step
#define F2_PER_CTA    128               // float2 per CTA per step
#define NUM_CTAS      (BATCH / LANES_PER_CTA)   // 256
#define T_REF    160.0f
#define MU_MIN   0.1f
#define MU_MAX   1.3f

// named barriers: FULL[slot] = producers arrive, consumers sync
//                 EMPTY[slot] = consumers arrive, producers sync
#define BAR_SYNC(id)   asm volatile("bar.sync %0, 256;"   :: "r"(id))
#define BAR_ARRIVE(id) asm volatile("bar.arrive %0, 256;" :: "r"(id))
// ids: FULL0=1, FULL1=2, EMPTY0=3, EMPTY1=4

struct Coef {
    float A, a_mu, a_mu2;
    float C, c_mu;
    float S, s_mu;
    float J, j_mu;
    float v0, v_mu;
};

__device__ __forceinline__ float fast_sigmoid(float x) {
    return __fdividef(1.0f, 1.0f + __expf(-x));
}
__device__ __forceinline__ float fast_softplus(float x) {
    return fmaxf(x, 0.0f) + __logf(1.0f + __expf(-fabsf(x)));
}

__device__ __forceinline__ void step_lane(const Coef& k, float& mu,
                                          float uc, float nc,
                                          float& pi, float& d1, float& s1,
                                          float& d2, float& s2, float& comp)
{
    const float x_pi = fmaf(mu, fmaf(mu, k.a_mu2, k.a_mu), k.A);
    pi = fast_sigmoid(x_pi);
    d1 = fmaf(mu, k.c_mu, k.C);
    s1 = fast_softplus(fmaf(mu, k.s_mu, k.S));
    d2 = fmaf(mu, k.j_mu, k.J);
    s2 = fast_softplus(fmaf(mu, k.v_mu, k.v0));

    const bool stay = uc < pi;
    comp = stay ? 0.0f : 1.0f;
    const float dmu = stay ? fmaf(s1, nc, d1) : fmaf(s2, nc, d2);
    mu = fminf(fmaxf(mu + dmu, MU_MIN), MU_MAX);
}

__global__ void __launch_bounds__(256)
galling_v6_kernel(const float* __restrict__ params,
                  const float* __restrict__ Tptr,
                  const float* __restrict__ u,
                  const float* __restrict__ noise,
                  float* __restrict__ out)
{
    // double-buffered staging: [slot][plane][256 floats] = 14 KB
    __shared__ __align__(16) float buf[2][7][LANES_PER_CTA];

    const int tid = threadIdx.x;

    if (tid < 128) {
        // ───────────────────────── producers: warps 0-3 ─────────────────
        const int p  = tid;                                   // 0..127
        const int b2 = blockIdx.x * F2_PER_CTA + p;           // float2 lane

        const float a0       = __ldg(params + 0);
        const float a_T      = __ldg(params + 1);
        const float a_mu     = __ldg(params + 2);
        const float a_mu2    = __ldg(params + 3);
        const float c0       = __ldg(params + 4);
        const float c_mu     = __ldg(params + 5);
        const float c_T      = __ldg(params + 6);
        const float s0       = __ldg(params + 7);
        const float s_mu     = __ldg(params + 8);
        const float s_T      = __ldg(params + 9);
        const float j0       = __ldg(params + 10);
        const float j_mu     = __ldg(params + 11);
        const float j_T      = __ldg(params + 12);
        const float v0       = __ldg(params + 13);
        const float v_mu     = __ldg(params + 14);
        const float mu0_base = __ldg(params + 15);
        const float mu0_T    = __ldg(params + 16);

        const float dT = __ldg(Tptr) - T_REF;

        Coef k;
        k.A = a0 + a_T * dT;  k.a_mu = a_mu;  k.a_mu2 = a_mu2;
        k.C = c0 + c_T * dT;  k.c_mu = c_mu;
        k.S = s0 + s_T * dT;  k.s_mu = s_mu;
        k.J = j0 + j_T * dT;  k.j_mu = j_mu;
        k.v0 = v0;            k.v_mu = v_mu;

        const float mu0 = fminf(fmaxf(mu0_base + mu0_T * dT, MU_MIN), MU_MAX);
        float mux = mu0, muy = mu0;

        const float2* __restrict__ up = (const float2*)u     + b2;
        const float2* __restrict__ np = (const float2*)noise + b2;

        // depth-2 prefetch (proven sufficient in R12: latency not binding)
        float2 ub[2], nb[2];
        ub[0] = __ldcs(up);         nb[0] = __ldcs(np);
        ub[1] = __ldcs(up + HALF);  nb[1] = __ldcs(np + HALF);

        for (int t = 0; t < N_CYCLES; ++t) {
            const int slot = t & 1;
            const float2 uc = ub[slot];
            const float2 nc = nb[slot];
            if (t + 2 < N_CYCLES) {
                const int off = (t + 2) * HALF;   // < 2^23, fits int
                ub[slot] = __ldcs(up + off);
                nb[slot] = __ldcs(np + off);
            }

            float pix, d1x, s1x, d2x, s2x, cx;
            float piy, d1y, s1y, d2y, s2y, cy;
            step_lane(k, mux, uc.x, nc.x, pix, d1x, s1x, d2x, s2x, cx);
            step_lane(k, muy, uc.y, nc.y, piy, d1y, s1y, d2y, s2y, cy);

            // wait until consumers drained this slot (t-2)
            if (t >= 2) BAR_SYNC(3 + slot);       // EMPTY[slot]

            ((float2*)buf[slot][0])[p] = make_float2(mux, muy);
            ((float2*)buf[slot][1])[p] = make_float2(cx,  cy);
            ((float2*)buf[slot][2])[p] = make_float2(pix, piy);
            ((float2*)buf[slot][3])[p] = make_float2(d1x, d1y);
            ((float2*)buf[slot][4])[p] = make_float2(s1x, s1y);
            ((float2*)buf[slot][5])[p] = make_float2(d2x, d2y);
            ((float2*)buf[slot][6])[p] = make_float2(s2x, s2y);

            BAR_ARRIVE(1 + slot);                 // FULL[slot]
        }
    } else {
        // ───────────────────────── consumers: warps 4-7 ─────────────────
        const int c = tid - 128;                  // 0..127
        const int g = c >> 6;                     // group 0/1
        const int w = c & 63;                     // 0..63, drains 4 floats
        const int base = blockIdx.x * LANES_PER_CTA + 4 * w;  // element off

        const int NB = N_CYCLES * BATCH;          // 9.83M < 2^31

        for (int t = 0; t < N_CYCLES; ++t) {
            const int slot = t & 1;
            BAR_SYNC(1 + slot);                   // FULL[slot]

            const int tb = t * BATCH + base;
            // group 0: planes 0,2,4,6   group 1: planes 1,3,5
            #pragma unroll
            for (int pl = 0; pl < 7; ++pl) {
                if ((pl & 1) == g) {
                    float4 v = *(const float4*)&buf[slot][pl][4 * w];
                    __stcs((float4*)(out + pl * NB + tb), v);
                }
            }

            BAR_ARRIVE(3 + slot);                 // EMPTY[slot]
        }
    }
}

extern "C" void kernel_launch(void* const* d_in, const int* in_sizes, int n_in,
                              void* d_out, int out_size)
{
    const float* params = (const float*)d_in[0];
    const float* T      = (const float*)d_in[1];
    const float* u      = (const float*)d_in[2];
    const float* noise  = (const float*)d_in[3];
    float* out          = (float*)d_out;

    galling_v6_kernel<<<NUM_CTAS, 256>>>(params, T, u, noise, out);
}

// round 15
// speedup vs baseline: 1.4568x; 1.4568x over previous
#include <cuda_runtime.h>

// InteractiveGallingModelV6 — v5: two-pass split.
//   Kernel A: serial 150-step chain, writes ONLY mu + component (78 MB).
//             mu stores use default caching so the plane stays in L2 for B.
//   Kernel B: fully parallel recompute of pi/d1/sigma1/d2/sigma2 from
//             mu[t-1] (L2 hits), float4 streaming writes (197 MB, .cs).
// R12/R13 falsified load-latency and store-backpressure models for the fused
// kernel; its ~1000cyc/iter floor scales with its memory work, so removing
// 5/7 of its stores and streaming them separately beats it.

#define N_CYCLES 150
#define BATCH    65536
#define HALF     (BATCH / 2)            // float2 lanes per step
#define QUARTER  (BATCH / 4)            // float4 lanes per step (16384 = 2^14)
#define NB       (N_CYCLES * BATCH)     // elements per plane (9,830,400)
#define T_REF    160.0f
#define MU_MIN   0.1f
#define MU_MAX   1.3f
#define PF_DEPTH 4

__device__ __forceinline__ float fast_sigmoid(float x) {
    return __fdividef(1.0f, 1.0f + __expf(-x));
}
__device__ __forceinline__ float fast_softplus(float x) {
    return fmaxf(x, 0.0f) + __logf(1.0f + __expf(-fabsf(x)));
}

// ─────────────────────────── Kernel A: the chain ──────────────────────────
__global__ void __launch_bounds__(128)
galling_chain_kernel(const float* __restrict__ params,
                     const float* __restrict__ Tptr,
                     const float* __restrict__ u,
                     const float* __restrict__ noise,
                     float* __restrict__ out)
{
    const int b = blockIdx.x * blockDim.x + threadIdx.x;   // float2 lane

    const float a0       = __ldg(params + 0);
    const float a_T      = __ldg(params + 1);
    const float a_mu     = __ldg(params + 2);
    const float a_mu2    = __ldg(params + 3);
    const float c0       = __ldg(params + 4);
    const float c_mu     = __ldg(params + 5);
    const float c_T      = __ldg(params + 6);
    const float s0       = __ldg(params + 7);
    const float s_mu     = __ldg(params + 8);
    const float s_T      = __ldg(params + 9);
    const float j0       = __ldg(params + 10);
    const float j_mu     = __ldg(params + 11);
    const float j_T      = __ldg(params + 12);
    const float v0       = __ldg(params + 13);
    const float v_mu     = __ldg(params + 14);
    const float mu0_base = __ldg(params + 15);
    const float mu0_T    = __ldg(params + 16);

    const float dT = __ldg(Tptr) - T_REF;

    const float A = a0 + a_T * dT;
    const float S = s0 + s_T * dT;
    const float J = j0 + j_T * dT;
    const float C = c0 + c_T * dT;   // only needed for delta path via d1
    (void)C;

    const float mu0 = fminf(fmaxf(mu0_base + mu0_T * dT, MU_MIN), MU_MAX);
    float mux = mu0, muy = mu0;

    const float2* __restrict__ up = (const float2*)u     + b;
    const float2* __restrict__ np = (const float2*)noise + b;

    float2* __restrict__ o0 = (float2*)out + b;                    // mu
    float2* __restrict__ o1 = o0 + (long long)N_CYCLES * HALF;     // component

    // depth-4 software pipeline (regs are cheap here)
    float2 ub[PF_DEPTH], nb[PF_DEPTH];
    #pragma unroll
    for (int i = 0; i < PF_DEPTH; ++i) {
        ub[i] = __ldcs(up + i * HALF);
        nb[i] = __ldcs(np + i * HALF);
    }

    const float Cd = c0 + c_T * dT;

    #pragma unroll 4
    for (int t = 0; t < N_CYCLES; ++t) {
        const int slot = t & (PF_DEPTH - 1);
        const float2 uc = ub[slot];
        const float2 nc = nb[slot];
        if (t + PF_DEPTH < N_CYCLES) {
            const int off = (t + PF_DEPTH) * HALF;
            ub[slot] = __ldcs(up + off);
            nb[slot] = __ldcs(np + off);
        }

        // lane x
        float pi  = fast_sigmoid(fmaf(mux, fmaf(mux, a_mu2, a_mu), A));
        bool  st  = uc.x < pi;
        float dmu = st ? fmaf(fast_softplus(fmaf(mux, s_mu, S)), nc.x, fmaf(mux, c_mu, Cd))
                       : fmaf(fast_softplus(fmaf(mux, v_mu, v0)), nc.x, fmaf(mux, j_mu, J));
        float cx  = st ? 0.0f : 1.0f;
        mux = fminf(fmaxf(mux + dmu, MU_MIN), MU_MAX);

        // lane y
        float piy = fast_sigmoid(fmaf(muy, fmaf(muy, a_mu2, a_mu), A));
        bool  sty = uc.y < piy;
        float dmy = sty ? fmaf(fast_softplus(fmaf(muy, s_mu, S)), nc.y, fmaf(muy, c_mu, Cd))
                        : fmaf(fast_softplus(fmaf(muy, v_mu, v0)), nc.y, fmaf(muy, j_mu, J));
        float cy  = sty ? 0.0f : 1.0f;
        muy = fminf(fmaxf(muy + dmy, MU_MIN), MU_MAX);

        const int idx = t * HALF;
        o0[idx] = make_float2(mux, muy);        // default caching: stay in L2 for B
        __stcs(o1 + idx, make_float2(cx, cy));  // component: never re-read
    }
}

// ─────────────────── Kernel B: parallel plane recompute ───────────────────
__global__ void __launch_bounds__(256)
galling_planes_kernel(const float* __restrict__ params,
                      const float* __restrict__ Tptr,
                      float* __restrict__ out)
{
    const int idx4 = blockIdx.x * blockDim.x + threadIdx.x;  // float4 item
    const int t  = idx4 >> 14;            // QUARTER == 2^14
    const int b4 = idx4 & (QUARTER - 1);

    const float a0       = __ldg(params + 0);
    const float a_T      = __ldg(params + 1);
    const float a_mu     = __ldg(params + 2);
    const float a_mu2    = __ldg(params + 3);
    const float c0       = __ldg(params + 4);
    const float c_mu     = __ldg(params + 5);
    const float c_T      = __ldg(params + 6);
    const float s0       = __ldg(params + 7);
    const float s_mu     = __ldg(params + 8);
    const float s_T      = __ldg(params + 9);
    const float j0       = __ldg(params + 10);
    const float j_mu     = __ldg(params + 11);
    const float j_T      = __ldg(params + 12);
    const float v0       = __ldg(params + 13);
    const float v_mu     = __ldg(params + 14);
    const float mu0_base = __ldg(params + 15);
    const float mu0_T    = __ldg(params + 16);

    const float dT = __ldg(Tptr) - T_REF;
    const float A  = a0 + a_T * dT;
    const float C  = c0 + c_T * dT;
    const float S  = s0 + s_T * dT;
    const float J  = j0 + j_T * dT;

    // mu at step entry = mu[t-1], or mu0 for t == 0
    float4 mp;
    if (t == 0) {
        const float mu0 = fminf(fmaxf(mu0_base + mu0_T * dT, MU_MIN), MU_MAX);
        mp = make_float4(mu0, mu0, mu0, mu0);
    } else {
        // plane 0 (mu history) written by kernel A — mostly L2 hits
        mp = __ldg((const float4*)out + (t - 1) * QUARTER + b4);
    }

    float4 pi4, d14, s14, d24, s24;
    {
        const float m[4] = {mp.x, mp.y, mp.z, mp.w};
        float pi[4], d1[4], s1[4], d2[4], s2[4];
        #pragma unroll
        for (int i = 0; i < 4; ++i) {
            const float mu = m[i];
            pi[i] = fast_sigmoid(fmaf(mu, fmaf(mu, a_mu2, a_mu), A));
            d1[i] = fmaf(mu, c_mu, C);
            s1[i] = fast_softplus(fmaf(mu, s_mu, S));
            d2[i] = fmaf(mu, j_mu, J);
            s2[i] = fast_softplus(fmaf(mu, v_mu, v0));
        }
        pi4 = make_float4(pi[0], pi[1], pi[2], pi[3]);
        d14 = make_float4(d1[0], d1[1], d1[2], d1[3]);
        s14 = make_float4(s1[0], s1[1], s1[2], s1[3]);
        d24 = make_float4(d2[0], d2[1], d2[2], d2[3]);
        s24 = make_float4(s2[0], s2[1], s2[2], s2[3]);
    }

    const int NB4  = N_CYCLES * QUARTER;        // float4 per plane
    const int base = t * QUARTER + b4;
    float4* o = (float4*)out;
    __stcs(o + 2 * NB4 + base, pi4);   // pi
    __stcs(o + 3 * NB4 + base, d14);   // d1
    __stcs(o + 4 * NB4 + base, s14);   // sigma1
    __stcs(o + 5 * NB4 + base, d24);   // d2
    __stcs(o + 6 * NB4 + base, s24);   // sigma2
}

extern "C" void kernel_launch(void* const* d_in, const int* in_sizes, int n_in,
                              void* d_out, int out_size)
{
    const float* params = (const float*)d_in[0];
    const float* T      = (const float*)d_in[1];
    const float* u      = (const float*)d_in[2];
    const float* noise  = (const float*)d_in[3];
    float* out          = (float*)d_out;

    // A: 32768 float2 lanes / 128 thr = 256 CTAs (R7's proven shape)
    galling_chain_kernel<<<HALF / 128, 128>>>(params, T, u, noise, out);

    // B: 150*16384 = 2,457,600 float4 items / 256 thr = 9600 CTAs
    galling_planes_kernel<<<(N_CYCLES * QUARTER) / 256, 256>>>(params, T, out);
}